// round 10
// baseline (speedup 1.0000x reference)
#include <cuda_runtime.h>
#include <math.h>

// LatentRNN: B=2048, T=512, P=8, L=64, H=180
// 128 persistent CTAs x 16 batch rows, 544 threads.
// Weights pre-packed per-k ([k][cols]) so each thread reads its n-column
// weight bundle with ONE coalesced vector LDG; thread tile m=8 x n=4 in the
// GRU GEMM cuts act LDS traffic 4x vs n=1.

#define B_    2048
#define T_    512
#define P_    8
#define L_    64
#define H_    180
#define IN_K  72
#define BT    16
#define NTHR  544
#define GST   20          // giT/ghT row stride (floats)

// packed weights, float-granular transposed layouts
__device__ float4 g_Wc4[180 * 270];   // [k][colgroup4] fused [W_ih | W_hh], 1080 cols
__device__ float2 g_Wb2[72 * 90];     // [k][colpair] W_in
__device__ float2 g_Wd2[244 * 90];    // [k][colpair] W_o1
__device__ float2 g_We2[180 * 32];    // [k][colpair] W_o2
__device__ float2 g_Wh2[64 * 90];     // [k][colpair] W_hp

#define N_C (180 * 270)
#define N_B (72 * 90)
#define N_D (244 * 90)
#define N_E (180 * 32)
#define N_H (64 * 90)

__global__ void prep_kernel(const float* __restrict__ Wih,
                            const float* __restrict__ Whh,
                            const float* __restrict__ Win,
                            const float* __restrict__ Wo1,
                            const float* __restrict__ Wo2,
                            const float* __restrict__ Whp)
{
    int i = blockIdx.x * blockDim.x + threadIdx.x;
    if (i < N_C) {
        int k = i / 270, g = i - k * 270;
        float v[4];
#pragma unroll
        for (int c = 0; c < 4; c++) {
            int j = 4 * g + c;
            v[c] = (j < 540) ? Wih[j * H_ + k] : Whh[(j - 540) * H_ + k];
        }
        g_Wc4[k * 270 + g] = make_float4(v[0], v[1], v[2], v[3]);
        return;
    }
    i -= N_C;
    if (i < N_B) {
        int k = i / 90, c = i - k * 90;
        g_Wb2[k * 90 + c] = make_float2(Win[(2*c) * IN_K + k], Win[(2*c+1) * IN_K + k]);
        return;
    }
    i -= N_B;
    if (i < N_D) {
        int k = i / 90, c = i - k * 90;
        g_Wd2[k * 90 + c] = make_float2(Wo1[(2*c) * 244 + k], Wo1[(2*c+1) * 244 + k]);
        return;
    }
    i -= N_D;
    if (i < N_E) {
        int k = i / 32, c = i - k * 32;
        g_We2[k * 32 + c] = make_float2(Wo2[(2*c) * H_ + k], Wo2[(2*c+1) * H_ + k]);
        return;
    }
    i -= N_E;
    if (i < N_H) {
        int k = i / 90, c = i - k * 90;
        g_Wh2[k * 90 + c] = make_float2(Whp[(2*c) * L_ + k], Whp[(2*c+1) * L_ + k]);
    }
}

struct __align__(16) Smem {
    float inT [IN_K][BT];      // [phys_t ; cur] transposed
    float xT  [H_][BT];        // gelu(in @ W_in^T)
    float hT  [2][H_][BT];     // hidden state, double buffered
    float oT  [H_][BT];        // gelu(cat @ W_o1^T)
    float giT [540][GST];      // gi (+bias); rows 0..179 overwritten with h_new
    float ghT [540][GST];      // gh (+bias)
    float catC[L_][BT];        // cur transposed (D's K 180..243)
    float cur [BT][L_];        // current latents, row-major
    float sb  [1684];          // ih 0 | hh 540 | in 1080 | o1 1260 | o2 1440 | hp 1504
};

__device__ __forceinline__ float gelu_f(float v) {
    return 0.5f * v * (1.0f + erff(v * 0.70710678118654752440f));
}
__device__ __forceinline__ float sigmoid_f(float v) {
    return 1.0f / (1.0f + expf(-v));
}

// 2-column x 8-row micro-GEMM over [k][90]-packed float2 weights.
// act base must be [K][BT] starting at row offset ro (uniform per warp).
template<int K, int LDW>
__device__ __forceinline__ void col2x8(const float2* __restrict__ w,
                                       const float* __restrict__ act,
                                       float* __restrict__ acc0,
                                       float* __restrict__ acc1)
{
#pragma unroll 4
    for (int k = 0; k < K; k++) {
        float2 w2 = w[k * LDW];
        const float* ak = act + k * BT;
        float4 a0 = *(const float4*)(ak);
        float4 a1 = *(const float4*)(ak + 4);
        acc0[0] = fmaf(a0.x, w2.x, acc0[0]); acc1[0] = fmaf(a0.x, w2.y, acc1[0]);
        acc0[1] = fmaf(a0.y, w2.x, acc0[1]); acc1[1] = fmaf(a0.y, w2.y, acc1[1]);
        acc0[2] = fmaf(a0.z, w2.x, acc0[2]); acc1[2] = fmaf(a0.z, w2.y, acc1[2]);
        acc0[3] = fmaf(a0.w, w2.x, acc0[3]); acc1[3] = fmaf(a0.w, w2.y, acc1[3]);
        acc0[4] = fmaf(a1.x, w2.x, acc0[4]); acc1[4] = fmaf(a1.x, w2.y, acc1[4]);
        acc0[5] = fmaf(a1.y, w2.x, acc0[5]); acc1[5] = fmaf(a1.y, w2.y, acc1[5]);
        acc0[6] = fmaf(a1.z, w2.x, acc0[6]); acc1[6] = fmaf(a1.z, w2.y, acc1[6]);
        acc0[7] = fmaf(a1.w, w2.x, acc0[7]); acc1[7] = fmaf(a1.w, w2.y, acc1[7]);
    }
}

__global__ __launch_bounds__(NTHR, 1)
void latent_rnn_kernel(const float* __restrict__ phys,
                       const float* __restrict__ latents,
                       const float* __restrict__ b_in,
                       const float* __restrict__ b_hp,
                       const float* __restrict__ b_ih,
                       const float* __restrict__ b_hh,
                       const float* __restrict__ b_o1,
                       const float* __restrict__ b_o2,
                       float* __restrict__ out)
{
    extern __shared__ char smem_raw[];
    Smem* s = reinterpret_cast<Smem*>(smem_raw);
    const int tid = threadIdx.x;
    const int b0  = blockIdx.x * BT;

    // ---- init ----
    for (int i = tid; i < BT * L_; i += NTHR) {
        int r = i >> 6, l = i & 63;
        float v = latents[(b0 + r) * L_ + l];
        s->cur[r][l] = v;
        s->inT[l][r] = v;
    }
    for (int i = tid; i < 540;  i += NTHR) s->sb[i]        = b_ih[i];
    for (int i = tid; i < 540;  i += NTHR) s->sb[540 + i]  = b_hh[i];
    for (int i = tid; i < 180;  i += NTHR) s->sb[1080 + i] = b_in[i];
    for (int i = tid; i < 180;  i += NTHR) s->sb[1260 + i] = b_o1[i];
    for (int i = tid; i < 64;   i += NTHR) s->sb[1440 + i] = b_o2[i];
    for (int i = tid; i < 180;  i += NTHR) s->sb[1504 + i] = b_hp[i];
    __syncthreads();

    // ---- h0 = latents @ W_hp^T + b_hp  (180 tasks: 2 cols x 8 rows) ----
    if (tid < 180) {
        const int q = tid / 90, c = tid - 90 * q, ro = q * 8;
        float acc0[8] = {0,0,0,0,0,0,0,0}, acc1[8] = {0,0,0,0,0,0,0,0};
        col2x8<L_, 90>(g_Wh2 + c, &s->inT[0][ro], acc0, acc1);
        const int j0 = 2 * c;
        float bb0 = s->sb[1504 + j0], bb1 = s->sb[1504 + j0 + 1];
#pragma unroll
        for (int i = 0; i < 8; i++) {
            s->hT[0][j0][ro + i]     = acc0[i] + bb0;
            s->hT[0][j0 + 1][ro + i] = acc1[i] + bb1;
        }
    }

    for (int t = 0; t < T_; t++) {
        const int cb = t & 1, nb = cb ^ 1;
        __syncthreads();   // (0) prev-E cur / h0 ready

        // ---- A: inT = [phys_t ; cur]^T ; catC = cur^T ----
        for (int i = tid; i < BT * IN_K; i += NTHR) {
            int r = i / IN_K, k = i - r * IN_K;
            s->inT[k][r] = (k < P_) ? phys[((size_t)(b0 + r) * T_ + t) * P_ + k]
                                    : s->cur[r][k - P_];
        }
        for (int i = tid; i < L_ * BT; i += NTHR) {
            int l = i >> 4, r = i & 15;
            s->catC[l][r] = s->cur[r][l];
        }
        __syncthreads();   // (1) inT / catC ready

        // ---- B: xT = gelu(inT @ W_in^T + b_in)  (180 tasks) ----
        if (tid < 180) {
            const int q = tid / 90, c = tid - 90 * q, ro = q * 8;
            float acc0[8] = {0,0,0,0,0,0,0,0}, acc1[8] = {0,0,0,0,0,0,0,0};
            col2x8<IN_K, 90>(g_Wb2 + c, &s->inT[0][ro], acc0, acc1);
            const int j0 = 2 * c;
            float bb0 = s->sb[1080 + j0], bb1 = s->sb[1080 + j0 + 1];
#pragma unroll
            for (int i = 0; i < 8; i++) {
                s->xT[j0][ro + i]     = gelu_f(acc0[i] + bb0);
                s->xT[j0 + 1][ro + i] = gelu_f(acc1[i] + bb1);
            }
        }
        __syncthreads();   // (2) xT ready

        // ---- C: gi/gh GEMMs. 540 tasks = (gi|gh) x rowhalf x 135 colgroups.
        //      Thread owns 4 contiguous cols x 8 rows; weight bundle is one
        //      coalesced float4 LDG per k; act reads warp-uniform. ----
        if (tid < 540) {
            const int half = (tid >= 270) ? 1 : 0;
            const int u    = tid - 270 * half;
            const int q    = u / 135;
            const int g    = u - 135 * q;
            const int gcol = 135 * half + g;       // 0..269; col = 4*gcol + c
            const int ro   = q * 8;
            const float* act = half ? &s->hT[cb][0][ro] : &s->xT[0][ro];
            const float4* wp = g_Wc4 + gcol;
            float acc[4][8];
#pragma unroll
            for (int c = 0; c < 4; c++)
#pragma unroll
                for (int i = 0; i < 8; i++) acc[c][i] = 0.f;
#pragma unroll 4
            for (int k = 0; k < H_; k++) {
                float4 w4 = wp[k * 270];
                const float* ak = act + k * BT;
                float4 a0 = *(const float4*)(ak);
                float4 a1 = *(const float4*)(ak + 4);
                float wv[4] = {w4.x, w4.y, w4.z, w4.w};
#pragma unroll
                for (int c = 0; c < 4; c++) {
                    acc[c][0] = fmaf(a0.x, wv[c], acc[c][0]);
                    acc[c][1] = fmaf(a0.y, wv[c], acc[c][1]);
                    acc[c][2] = fmaf(a0.z, wv[c], acc[c][2]);
                    acc[c][3] = fmaf(a0.w, wv[c], acc[c][3]);
                    acc[c][4] = fmaf(a1.x, wv[c], acc[c][4]);
                    acc[c][5] = fmaf(a1.y, wv[c], acc[c][5]);
                    acc[c][6] = fmaf(a1.z, wv[c], acc[c][6]);
                    acc[c][7] = fmaf(a1.w, wv[c], acc[c][7]);
                }
            }
#pragma unroll
            for (int c = 0; c < 4; c++) {
                const int col = 4 * gcol + c;      // 0..1079
                float bb = s->sb[col];
                float* dst = half ? &s->ghT[col - 540][ro] : &s->giT[col][ro];
                float4 f0 = make_float4(acc[c][0] + bb, acc[c][1] + bb,
                                        acc[c][2] + bb, acc[c][3] + bb);
                float4 f1 = make_float4(acc[c][4] + bb, acc[c][5] + bb,
                                        acc[c][6] + bb, acc[c][7] + bb);
                *(float4*)dst       = f0;
                *(float4*)(dst + 4) = f1;
            }
        }
        __syncthreads();   // (3) gi/gh ready

        // ---- gates: h_new -> hT[nb]; giT[0..179] := h_new ----
        for (int i = tid; i < H_ * BT; i += NTHR) {
            int j = i >> 4, r = i & 15;
            float rg = sigmoid_f(s->giT[j][r]        + s->ghT[j][r]);
            float zg = sigmoid_f(s->giT[j + H_][r]   + s->ghT[j + H_][r]);
            float ng = tanhf    (s->giT[j + 2*H_][r] + rg * s->ghT[j + 2*H_][r]);
            float hn = (1.f - zg) * ng + zg * s->hT[cb][j][r];
            s->hT[nb][j][r] = hn;
            s->giT[j][r] = hn;      // owned element, read-before-write above
        }
        __syncthreads();   // (4) h_new / giT ready

        // ---- D: oT = gelu([h_new ; cur] @ W_o1^T + b_o1)  (180 tasks) ----
        if (tid < 180) {
            const int q = tid / 90, c = tid - 90 * q, ro = q * 8;
            float acc0[8] = {0,0,0,0,0,0,0,0}, acc1[8] = {0,0,0,0,0,0,0,0};
            // K 0..179: h_new (giT rows, stride GST)
#pragma unroll 4
            for (int k = 0; k < H_; k++) {
                float2 w2 = g_Wd2[k * 90 + c];
                const float* ak = &s->giT[k][ro];
                float4 a0 = *(const float4*)(ak);
                float4 a1 = *(const float4*)(ak + 4);
                acc0[0] = fmaf(a0.x, w2.x, acc0[0]); acc1[0] = fmaf(a0.x, w2.y, acc1[0]);
                acc0[1] = fmaf(a0.y, w2.x, acc0[1]); acc1[1] = fmaf(a0.y, w2.y, acc1[1]);
                acc0[2] = fmaf(a0.z, w2.x, acc0[2]); acc1[2] = fmaf(a0.z, w2.y, acc1[2]);
                acc0[3] = fmaf(a0.w, w2.x, acc0[3]); acc1[3] = fmaf(a0.w, w2.y, acc1[3]);
                acc0[4] = fmaf(a1.x, w2.x, acc0[4]); acc1[4] = fmaf(a1.x, w2.y, acc1[4]);
                acc0[5] = fmaf(a1.y, w2.x, acc0[5]); acc1[5] = fmaf(a1.y, w2.y, acc1[5]);
                acc0[6] = fmaf(a1.z, w2.x, acc0[6]); acc1[6] = fmaf(a1.z, w2.y, acc1[6]);
                acc0[7] = fmaf(a1.w, w2.x, acc0[7]); acc1[7] = fmaf(a1.w, w2.y, acc1[7]);
            }
            // K 180..243: cur (catC)
            col2x8<L_, 90>(g_Wd2 + 180 * 90 + c, &s->catC[0][ro], acc0, acc1);
            const int j0 = 2 * c;
            float bb0 = s->sb[1260 + j0], bb1 = s->sb[1260 + j0 + 1];
#pragma unroll
            for (int i = 0; i < 8; i++) {
                s->oT[j0][ro + i]     = gelu_f(acc0[i] + bb0);
                s->oT[j0 + 1][ro + i] = gelu_f(acc1[i] + bb1);
            }
        }
        __syncthreads();   // (5) oT ready

        // ---- E: delta = oT @ W_o2^T + b_o2; cur = clip(cur+delta); store ----
        if (tid < 128) {
            const int q = tid >> 5, g = tid & 31, ro = q * 4;
            float a0[4] = {0,0,0,0}, a1[4] = {0,0,0,0};
#pragma unroll 4
            for (int k = 0; k < H_; k++) {
                float2 w2 = g_We2[k * 32 + g];
                float4 a = *(const float4*)&s->oT[k][ro];
                a0[0] = fmaf(a.x, w2.x, a0[0]); a1[0] = fmaf(a.x, w2.y, a1[0]);
                a0[1] = fmaf(a.y, w2.x, a0[1]); a1[1] = fmaf(a.y, w2.y, a1[1]);
                a0[2] = fmaf(a.z, w2.x, a0[2]); a1[2] = fmaf(a.z, w2.y, a1[2]);
                a0[3] = fmaf(a.w, w2.x, a0[3]); a1[3] = fmaf(a.w, w2.y, a1[3]);
            }
            const int j0 = 2 * g;
            float bb0 = s->sb[1440 + j0], bb1 = s->sb[1440 + j0 + 1];
#pragma unroll
            for (int i = 0; i < 4; i++) {
                int r = ro + i;
                float c0 = fminf(fmaxf(s->cur[r][j0]     + a0[i] + bb0, 0.f), 1.f);
                float c1 = fminf(fmaxf(s->cur[r][j0 + 1] + a1[i] + bb1, 0.f), 1.f);
                s->cur[r][j0]     = c0;
                s->cur[r][j0 + 1] = c1;
                out[((size_t)(b0 + r) * T_ + t) * L_ + j0]     = c0;
                out[((size_t)(b0 + r) * T_ + t) * L_ + j0 + 1] = c1;
            }
        }
    }
}

extern "C" void kernel_launch(void* const* d_in, const int* in_sizes, int n_in,
                              void* d_out, int out_size)
{
    const float* phys    = (const float*)d_in[0];
    const float* latents = (const float*)d_in[1];
    const float* W_in    = (const float*)d_in[2];
    const float* b_in    = (const float*)d_in[3];
    const float* W_hp    = (const float*)d_in[4];
    const float* b_hp    = (const float*)d_in[5];
    const float* W_ih    = (const float*)d_in[6];
    const float* b_ih    = (const float*)d_in[7];
    const float* W_hh    = (const float*)d_in[8];
    const float* b_hh    = (const float*)d_in[9];
    const float* W_o1    = (const float*)d_in[10];
    const float* b_o1    = (const float*)d_in[11];
    const float* W_o2    = (const float*)d_in[12];
    const float* b_o2    = (const float*)d_in[13];
    float* out = (float*)d_out;

    static bool attr_set = false;
    if (!attr_set) {
        cudaFuncSetAttribute(latent_rnn_kernel,
                             cudaFuncAttributeMaxDynamicSharedMemorySize,
                             (int)sizeof(Smem));
        attr_set = true;
    }

    prep_kernel<<<(N_C + N_B + N_D + N_E + N_H + 255) / 256, 256>>>(
        W_ih, W_hh, W_in, W_o1, W_o2, W_hp);

    latent_rnn_kernel<<<B_ / BT, NTHR, sizeof(Smem)>>>(
        phys, latents, b_in, b_hp, b_ih, b_hh, b_o1, b_o2, out);
}

// round 11
// speedup vs baseline: 1.0889x; 1.0889x over previous
#include <cuda_runtime.h>
#include <math.h>

// LatentRNN: B=2048, T=512, P=8, L=64, H=180
// 256 persistent CTAs x 8 batch rows, 544 threads, 2 CTAs/SM co-resident.
// Low-L1 tiling (R10) + doubled warp residency: n=4 x m=4 GRU GEMM with one
// coalesced weight LDG.128 and one act LDS.128 per 16 FMA.

#define B_    2048
#define T_    512
#define P_    8
#define L_    64
#define H_    180
#define IN_K  72
#define BT    8
#define NTHR  544
#define GRID  (B_ / BT)

// packed weights, float-granular transposed layouts (same as R10)
__device__ float4 g_Wc4[180 * 270];   // [k][colgroup4] fused [W_ih | W_hh], 1080 cols
__device__ float2 g_Wb2[72 * 90];     // [k][colpair] W_in
__device__ float2 g_Wd2[244 * 90];    // [k][colpair] W_o1
__device__ float2 g_We2[180 * 32];    // [k][colpair] W_o2
__device__ float2 g_Wh2[64 * 90];     // [k][colpair] W_hp

#define N_C (180 * 270)
#define N_B (72 * 90)
#define N_D (244 * 90)
#define N_E (180 * 32)
#define N_H (64 * 90)

__global__ void prep_kernel(const float* __restrict__ Wih,
                            const float* __restrict__ Whh,
                            const float* __restrict__ Win,
                            const float* __restrict__ Wo1,
                            const float* __restrict__ Wo2,
                            const float* __restrict__ Whp)
{
    int i = blockIdx.x * blockDim.x + threadIdx.x;
    if (i < N_C) {
        int k = i / 270, g = i - k * 270;
        float v[4];
#pragma unroll
        for (int c = 0; c < 4; c++) {
            int j = 4 * g + c;
            v[c] = (j < 540) ? Wih[j * H_ + k] : Whh[(j - 540) * H_ + k];
        }
        g_Wc4[k * 270 + g] = make_float4(v[0], v[1], v[2], v[3]);
        return;
    }
    i -= N_C;
    if (i < N_B) {
        int k = i / 90, c = i - k * 90;
        g_Wb2[k * 90 + c] = make_float2(Win[(2*c) * IN_K + k], Win[(2*c+1) * IN_K + k]);
        return;
    }
    i -= N_B;
    if (i < N_D) {
        int k = i / 90, c = i - k * 90;
        g_Wd2[k * 90 + c] = make_float2(Wo1[(2*c) * 244 + k], Wo1[(2*c+1) * 244 + k]);
        return;
    }
    i -= N_D;
    if (i < N_E) {
        int k = i / 32, c = i - k * 32;
        g_We2[k * 32 + c] = make_float2(Wo2[(2*c) * H_ + k], Wo2[(2*c+1) * H_ + k]);
        return;
    }
    i -= N_E;
    if (i < N_H) {
        int k = i / 90, c = i - k * 90;
        g_Wh2[k * 90 + c] = make_float2(Whp[(2*c) * L_ + k], Whp[(2*c+1) * L_ + k]);
    }
}

struct __align__(16) Smem {
    float inT [IN_K][BT];      // [phys_t ; cur] transposed
    float xT  [H_][BT];        // gelu(in @ W_in^T)
    float hT  [2][H_][BT];     // hidden state, double buffered
    float oT  [H_][BT];        // gelu(cat @ W_o1^T)
    float giT [540][BT];       // gi (+bias); rows 0..179 overwritten with h_new
    float ghT [540][BT];       // gh (+bias)
    float catC[L_][BT];        // cur transposed (D's K 180..243)
    float cur [BT][L_];        // current latents, row-major
    float sb  [1684];          // ih 0 | hh 540 | in 1080 | o1 1260 | o2 1440 | hp 1504
};

__device__ __forceinline__ float gelu_f(float v) {
    return 0.5f * v * (1.0f + erff(v * 0.70710678118654752440f));
}
__device__ __forceinline__ float sigmoid_f(float v) {
    return 1.0f / (1.0f + expf(-v));
}

// 2 cols x 4 rows micro-GEMM over [k][LDW]-packed float2 weights.
// act is [K][BT] starting at row offset ro.
template<int K, int LDW>
__device__ __forceinline__ void col2x4(const float2* __restrict__ w,
                                       const float* __restrict__ act,
                                       float* __restrict__ acc0,
                                       float* __restrict__ acc1)
{
#pragma unroll 4
    for (int k = 0; k < K; k++) {
        float2 w2 = w[k * LDW];
        float4 a = *(const float4*)(act + k * BT);
        acc0[0] = fmaf(a.x, w2.x, acc0[0]); acc1[0] = fmaf(a.x, w2.y, acc1[0]);
        acc0[1] = fmaf(a.y, w2.x, acc0[1]); acc1[1] = fmaf(a.y, w2.y, acc1[1]);
        acc0[2] = fmaf(a.z, w2.x, acc0[2]); acc1[2] = fmaf(a.z, w2.y, acc1[2]);
        acc0[3] = fmaf(a.w, w2.x, acc0[3]); acc1[3] = fmaf(a.w, w2.y, acc1[3]);
    }
}

__global__ __launch_bounds__(NTHR, 2)
void latent_rnn_kernel(const float* __restrict__ phys,
                       const float* __restrict__ latents,
                       const float* __restrict__ b_in,
                       const float* __restrict__ b_hp,
                       const float* __restrict__ b_ih,
                       const float* __restrict__ b_hh,
                       const float* __restrict__ b_o1,
                       const float* __restrict__ b_o2,
                       float* __restrict__ out)
{
    extern __shared__ char smem_raw[];
    Smem* s = reinterpret_cast<Smem*>(smem_raw);
    const int tid = threadIdx.x;
    const int b0  = blockIdx.x * BT;

    // ---- init ----
    for (int i = tid; i < BT * L_; i += NTHR) {
        int r = i >> 6, l = i & 63;
        float v = latents[(b0 + r) * L_ + l];
        s->cur[r][l]  = v;
        s->catC[l][r] = v;       // latents^T for h0
    }
    for (int i = tid; i < 540;  i += NTHR) s->sb[i]        = b_ih[i];
    for (int i = tid; i < 540;  i += NTHR) s->sb[540 + i]  = b_hh[i];
    for (int i = tid; i < 180;  i += NTHR) s->sb[1080 + i] = b_in[i];
    for (int i = tid; i < 180;  i += NTHR) s->sb[1260 + i] = b_o1[i];
    for (int i = tid; i < 64;   i += NTHR) s->sb[1440 + i] = b_o2[i];
    for (int i = tid; i < 180;  i += NTHR) s->sb[1504 + i] = b_hp[i];
    __syncthreads();

    // ---- h0 = latents @ W_hp^T + b_hp  (180 tasks: 2 cols x 4 rows) ----
    if (tid < 180) {
        const int c = tid >> 1, ro = (tid & 1) * 4;
        float acc0[4] = {0,0,0,0}, acc1[4] = {0,0,0,0};
        col2x4<L_, 90>(g_Wh2 + c, &s->catC[0][ro], acc0, acc1);
        const int j0 = 2 * c;
        float bb0 = s->sb[1504 + j0], bb1 = s->sb[1504 + j0 + 1];
#pragma unroll
        for (int i = 0; i < 4; i++) {
            s->hT[0][j0][ro + i]     = acc0[i] + bb0;
            s->hT[0][j0 + 1][ro + i] = acc1[i] + bb1;
        }
    }

    for (int t = 0; t < T_; t++) {
        const int cb = t & 1, nb = cb ^ 1;
        __syncthreads();   // (0) prev-E cur / h0 ready

        // ---- A: inT = [phys_t ; cur]^T ; catC = cur^T ----
        for (int i = tid; i < BT * IN_K; i += NTHR) {
            int r = i / IN_K, k = i - r * IN_K;
            s->inT[k][r] = (k < P_) ? phys[((size_t)(b0 + r) * T_ + t) * P_ + k]
                                    : s->cur[r][k - P_];
        }
        for (int i = tid; i < L_ * BT; i += NTHR) {
            int l = i >> 3, r = i & 7;
            s->catC[l][r] = s->cur[r][l];
        }
        __syncthreads();   // (1) inT / catC ready

        // ---- B: xT = gelu(inT @ W_in^T + b_in)  (180 tasks) ----
        if (tid < 180) {
            const int c = tid >> 1, ro = (tid & 1) * 4;
            float acc0[4] = {0,0,0,0}, acc1[4] = {0,0,0,0};
            col2x4<IN_K, 90>(g_Wb2 + c, &s->inT[0][ro], acc0, acc1);
            const int j0 = 2 * c;
            float bb0 = s->sb[1080 + j0], bb1 = s->sb[1080 + j0 + 1];
#pragma unroll
            for (int i = 0; i < 4; i++) {
                s->xT[j0][ro + i]     = gelu_f(acc0[i] + bb0);
                s->xT[j0 + 1][ro + i] = gelu_f(acc1[i] + bb1);
            }
        }
        __syncthreads();   // (2) xT ready

        // ---- C: gi/gh GEMMs. 540 tasks = 270 colgroups(4) x 2 rowgroups(4).
        //      One coalesced LDG.128 weight + one LDS.128 act per k, 16 FMA. ----
        if (tid < 540) {
            const int gcol = tid >> 1;            // 0..269
            const int ro   = (tid & 1) * 4;
            const bool gh  = (gcol >= 135);       // cols 540..1079
            const float* act = gh ? &s->hT[cb][0][ro] : &s->xT[0][ro];
            const float4* wp = g_Wc4 + gcol;
            float acc[4][4];
#pragma unroll
            for (int c = 0; c < 4; c++)
#pragma unroll
                for (int i = 0; i < 4; i++) acc[c][i] = 0.f;
#pragma unroll 4
            for (int k = 0; k < H_; k++) {
                float4 w4 = wp[k * 270];
                float4 a  = *(const float4*)(act + k * BT);
                acc[0][0] = fmaf(a.x, w4.x, acc[0][0]);
                acc[0][1] = fmaf(a.y, w4.x, acc[0][1]);
                acc[0][2] = fmaf(a.z, w4.x, acc[0][2]);
                acc[0][3] = fmaf(a.w, w4.x, acc[0][3]);
                acc[1][0] = fmaf(a.x, w4.y, acc[1][0]);
                acc[1][1] = fmaf(a.y, w4.y, acc[1][1]);
                acc[1][2] = fmaf(a.z, w4.y, acc[1][2]);
                acc[1][3] = fmaf(a.w, w4.y, acc[1][3]);
                acc[2][0] = fmaf(a.x, w4.z, acc[2][0]);
                acc[2][1] = fmaf(a.y, w4.z, acc[2][1]);
                acc[2][2] = fmaf(a.z, w4.z, acc[2][2]);
                acc[2][3] = fmaf(a.w, w4.z, acc[2][3]);
                acc[3][0] = fmaf(a.x, w4.w, acc[3][0]);
                acc[3][1] = fmaf(a.y, w4.w, acc[3][1]);
                acc[3][2] = fmaf(a.z, w4.w, acc[3][2]);
                acc[3][3] = fmaf(a.w, w4.w, acc[3][3]);
            }
#pragma unroll
            for (int c = 0; c < 4; c++) {
                const int col = 4 * gcol + c;     // 0..1079
                float bb = s->sb[col];
                float* dst = gh ? &s->ghT[col - 540][ro] : &s->giT[col][ro];
                *(float4*)dst = make_float4(acc[c][0] + bb, acc[c][1] + bb,
                                            acc[c][2] + bb, acc[c][3] + bb);
            }
        }
        __syncthreads();   // (3) gi/gh ready

        // ---- gates: h_new -> hT[nb]; giT[0..179] := h_new ----
        for (int i = tid; i < H_ * BT; i += NTHR) {
            int j = i >> 3, r = i & 7;
            float rg = sigmoid_f(s->giT[j][r]        + s->ghT[j][r]);
            float zg = sigmoid_f(s->giT[j + H_][r]   + s->ghT[j + H_][r]);
            float ng = tanhf    (s->giT[j + 2*H_][r] + rg * s->ghT[j + 2*H_][r]);
            float hn = (1.f - zg) * ng + zg * s->hT[cb][j][r];
            s->hT[nb][j][r] = hn;
            s->giT[j][r] = hn;      // owned element, read-before-write above
        }
        __syncthreads();   // (4) h_new / giT ready

        // ---- D: oT = gelu([h_new ; cur] @ W_o1^T + b_o1)  (180 tasks) ----
        if (tid < 180) {
            const int c = tid >> 1, ro = (tid & 1) * 4;
            float acc0[4] = {0,0,0,0}, acc1[4] = {0,0,0,0};
            col2x4<H_, 90>(g_Wd2 + c, &s->giT[0][ro], acc0, acc1);             // K 0..179
            col2x4<L_, 90>(g_Wd2 + 180 * 90 + c, &s->catC[0][ro], acc0, acc1); // K 180..243
            const int j0 = 2 * c;
            float bb0 = s->sb[1260 + j0], bb1 = s->sb[1260 + j0 + 1];
#pragma unroll
            for (int i = 0; i < 4; i++) {
                s->oT[j0][ro + i]     = gelu_f(acc0[i] + bb0);
                s->oT[j0 + 1][ro + i] = gelu_f(acc1[i] + bb1);
            }
        }
        __syncthreads();   // (5) oT ready

        // ---- E: delta = oT @ W_o2^T + b_o2; cur = clip(cur+delta); store ----
        if (tid < 64) {
            const int g = tid >> 1, ro = (tid & 1) * 4;
            float a0[4] = {0,0,0,0}, a1[4] = {0,0,0,0};
            col2x4<H_, 32>(g_We2 + g, &s->oT[0][ro], a0, a1);
            const int j0 = 2 * g;
            float bb0 = s->sb[1440 + j0], bb1 = s->sb[1440 + j0 + 1];
#pragma unroll
            for (int i = 0; i < 4; i++) {
                int r = ro + i;
                float c0 = fminf(fmaxf(s->cur[r][j0]     + a0[i] + bb0, 0.f), 1.f);
                float c1 = fminf(fmaxf(s->cur[r][j0 + 1] + a1[i] + bb1, 0.f), 1.f);
                s->cur[r][j0]     = c0;
                s->cur[r][j0 + 1] = c1;
                out[((size_t)(b0 + r) * T_ + t) * L_ + j0]     = c0;
                out[((size_t)(b0 + r) * T_ + t) * L_ + j0 + 1] = c1;
            }
        }
    }
}

extern "C" void kernel_launch(void* const* d_in, const int* in_sizes, int n_in,
                              void* d_out, int out_size)
{
    const float* phys    = (const float*)d_in[0];
    const float* latents = (const float*)d_in[1];
    const float* W_in    = (const float*)d_in[2];
    const float* b_in    = (const float*)d_in[3];
    const float* W_hp    = (const float*)d_in[4];
    const float* b_hp    = (const float*)d_in[5];
    const float* W_ih    = (const float*)d_in[6];
    const float* b_ih    = (const float*)d_in[7];
    const float* W_hh    = (const float*)d_in[8];
    const float* b_hh    = (const float*)d_in[9];
    const float* W_o1    = (const float*)d_in[10];
    const float* b_o1    = (const float*)d_in[11];
    const float* W_o2    = (const float*)d_in[12];
    const float* b_o2    = (const float*)d_in[13];
    float* out = (float*)d_out;

    static bool attr_set = false;
    if (!attr_set) {
        cudaFuncSetAttribute(latent_rnn_kernel,
                             cudaFuncAttributeMaxDynamicSharedMemorySize,
                             (int)sizeof(Smem));
        attr_set = true;
    }

    prep_kernel<<<(N_C + N_B + N_D + N_E + N_H + 255) / 256, 256>>>(
        W_ih, W_hh, W_in, W_o1, W_o2, W_hp);

    latent_rnn_kernel<<<GRID, NTHR, sizeof(Smem)>>>(
        phys, latents, b_in, b_hp, b_ih, b_hh, b_o1, b_o2, out);
}